// round 15
// baseline (speedup 1.0000x reference)
#include <cuda_runtime.h>
#include <math.h>
#include <stdint.h>

// ---------------------------------------------------------------------------
// mLSTM cell, B=128, D_IN=1024, H=1024  (SIMT + FFMA2; plain sm_103 target)
// output: concat[ h_new (128*1024), C_new (128*1024*1024), n_new (128*1024) ]
// ---------------------------------------------------------------------------

#define Bsz   128
#define Hdim  1024
#define NQKV  3072
#define KSPLIT 6
#define OUTMN (Bsz * NQKV)

__device__ float g_qkv[Bsz * NQKV];        // [b][ q | k | v ]
__device__ float g_ifo[Bsz * NQKV];        // [b][ i | f | o ]
__device__ float g_part[KSPLIT * OUTMN];
__device__ float g_hpart[8 * Bsz * Hdim];
__device__ float g_denom[Bsz];

// ---- packed f32x2 helpers ----
__device__ __forceinline__ unsigned long long pack_dup(float a) {
    unsigned long long r;
    uint32_t au = __float_as_uint(a);
    asm("mov.b64 %0, {%1, %1};" : "=l"(r) : "r"(au));
    return r;
}
__device__ __forceinline__ void fma2(unsigned long long& d,
                                     unsigned long long a,
                                     unsigned long long b) {
    asm("fma.rn.f32x2 %0, %1, %2, %0;" : "+l"(d) : "l"(a), "l"(b));
}
__device__ __forceinline__ float2 unpack2(unsigned long long v) {
    uint32_t lo, hi;
    asm("mov.b64 {%0, %1}, %2;" : "=r"(lo), "=r"(hi) : "l"(v));
    return make_float2(__uint_as_float(lo), __uint_as_float(hi));
}
__device__ __forceinline__ uint32_t smem_u32(const void* p) {
    uint32_t a;
    asm("{ .reg .u64 t; cvta.to.shared.u64 t, %1; cvt.u32.u64 %0, t; }"
        : "=r"(a) : "l"(p));
    return a;
}
__device__ __forceinline__ void cp_async16(uint32_t dst, const float* src) {
    asm volatile("cp.async.cg.shared.global [%0], [%1], 16;"
                 :: "r"(dst), "l"(src));
}

// ---------------------------------------------------------------------------
// Split-K GEMM mainloop (round-9/12 form): BM=128 BN=128 BK=16,
// 256 threads, 8x8 FFMA2 tile, double-buffered smem. grid (24,1,6).
// ---------------------------------------------------------------------------
template <int MODE>
__global__ __launch_bounds__(256) void gemm_main_kernel(
    const float* __restrict__ Aext, const float* __restrict__ W)
{
    const float* __restrict__ A = (MODE == 0) ? Aext : (const float*)(g_qkv + 2048);
    const int lda = (MODE == 0) ? 1024 : NQKV;
    const int ldw = (MODE == 0) ? 4096 : 3072;

    __shared__ float As[2][16][132];
    __shared__ float Bs[2][16][128];

    const int tid = threadIdx.x;
    const int bn = blockIdx.x * 128;
    const int kz = blockIdx.z;

    const int aRow = tid >> 1;
    const int aK   = (tid & 1) * 8;
    const int bRow = tid >> 4;
    const int bCol = (tid & 15) * 8;

    const int mrow = (tid >> 4) * 8;
    const int ncol = (tid & 15) * 8;

    unsigned long long acc2[8][4];
#pragma unroll
    for (int r = 0; r < 8; r++)
#pragma unroll
        for (int c = 0; c < 4; c++) acc2[r][c] = 0ull;

    const int it0   = kz * 10 + (kz < 4 ? kz : 4);
    const int iters = (kz < 4) ? 11 : 10;

    {
        const int k0 = it0 * 16;
        float4 av0 = *(const float4*)(A + (size_t)aRow * lda + k0 + aK);
        float4 av1 = *(const float4*)(A + (size_t)aRow * lda + k0 + aK + 4);
        As[0][aK + 0][aRow] = av0.x; As[0][aK + 1][aRow] = av0.y;
        As[0][aK + 2][aRow] = av0.z; As[0][aK + 3][aRow] = av0.w;
        As[0][aK + 4][aRow] = av1.x; As[0][aK + 5][aRow] = av1.y;
        As[0][aK + 6][aRow] = av1.z; As[0][aK + 7][aRow] = av1.w;
        float4 bv0 = *(const float4*)(W + (size_t)(k0 + bRow) * ldw + bn + bCol);
        float4 bv1 = *(const float4*)(W + (size_t)(k0 + bRow) * ldw + bn + bCol + 4);
        *(float4*)&Bs[0][bRow][bCol]     = bv0;
        *(float4*)&Bs[0][bRow][bCol + 4] = bv1;
    }
    __syncthreads();

    int cur = 0;
    for (int it = 0; it < iters; it++) {
        const bool has = (it + 1 < iters);
        float4 av0, av1, bv0, bv1;
        if (has) {
            const int k0 = (it0 + it + 1) * 16;
            av0 = *(const float4*)(A + (size_t)aRow * lda + k0 + aK);
            av1 = *(const float4*)(A + (size_t)aRow * lda + k0 + aK + 4);
            bv0 = *(const float4*)(W + (size_t)(k0 + bRow) * ldw + bn + bCol);
            bv1 = *(const float4*)(W + (size_t)(k0 + bRow) * ldw + bn + bCol + 4);
        }

#pragma unroll
        for (int kk = 0; kk < 16; kk++) {
            float4 a0 = *(const float4*)&As[cur][kk][mrow];
            float4 a1 = *(const float4*)&As[cur][kk][mrow + 4];
            ulonglong2 bb0 = *(const ulonglong2*)&Bs[cur][kk][ncol];
            ulonglong2 bb1 = *(const ulonglong2*)&Bs[cur][kk][ncol + 4];
            unsigned long long a2[8];
            a2[0] = pack_dup(a0.x); a2[1] = pack_dup(a0.y);
            a2[2] = pack_dup(a0.z); a2[3] = pack_dup(a0.w);
            a2[4] = pack_dup(a1.x); a2[5] = pack_dup(a1.y);
            a2[6] = pack_dup(a1.z); a2[7] = pack_dup(a1.w);
#pragma unroll
            for (int r = 0; r < 8; r++) {
                fma2(acc2[r][0], a2[r], bb0.x);
                fma2(acc2[r][1], a2[r], bb0.y);
                fma2(acc2[r][2], a2[r], bb1.x);
                fma2(acc2[r][3], a2[r], bb1.y);
            }
        }

        if (has) {
            const int nxt = cur ^ 1;
            As[nxt][aK + 0][aRow] = av0.x; As[nxt][aK + 1][aRow] = av0.y;
            As[nxt][aK + 2][aRow] = av0.z; As[nxt][aK + 3][aRow] = av0.w;
            As[nxt][aK + 4][aRow] = av1.x; As[nxt][aK + 5][aRow] = av1.y;
            As[nxt][aK + 6][aRow] = av1.z; As[nxt][aK + 7][aRow] = av1.w;
            *(float4*)&Bs[nxt][bRow][bCol]     = bv0;
            *(float4*)&Bs[nxt][bRow][bCol + 4] = bv1;
            __syncthreads();
            cur = nxt;
        }
    }

    float* __restrict__ part = g_part + (size_t)kz * OUTMN;
#pragma unroll
    for (int r = 0; r < 8; r++) {
        int m = mrow + r;
        float2 p0 = unpack2(acc2[r][0]);
        float2 p1 = unpack2(acc2[r][1]);
        float2 p2 = unpack2(acc2[r][2]);
        float2 p3 = unpack2(acc2[r][3]);
        *(float4*)(part + (size_t)m * NQKV + bn + ncol) =
            make_float4(p0.x, p0.y, p1.x, p1.y);
        *(float4*)(part + (size_t)m * NQKV + bn + ncol + 4) =
            make_float4(p2.x, p2.y, p3.x, p3.y);
    }
}

// ---------------------------------------------------------------------------
// GEMM epilogue
// ---------------------------------------------------------------------------
template <int MODE>
__global__ __launch_bounds__(256) void gemm_epi_kernel(const float* __restrict__ bias)
{
    const int idx = blockIdx.x * 256 + threadIdx.x;
    const int nn = idx % NQKV;
    float v = bias[nn];
#pragma unroll
    for (int p = 0; p < KSPLIT; p++) v += g_part[(size_t)p * OUTMN + idx];
    if (MODE == 0) {
        if (nn < 2048) v = tanhf(v);
        g_qkv[idx] = v;
    } else {
        g_ifo[idx] = 1.0f / (1.0f + expf(-v));
    }
}

// ---------------------------------------------------------------------------
// n_new + denom
// ---------------------------------------------------------------------------
__global__ __launch_bounds__(256) void nnew_denom_kernel(
    const float* __restrict__ n_in, float* __restrict__ out_n)
{
    const int b = blockIdx.x;
    const int tid = threadIdx.x;
    __shared__ float red[256];

    float psum = 0.f;
#pragma unroll
    for (int d = tid; d < Hdim; d += 256) {
        float iv = g_ifo[b * NQKV + d];
        float fv = g_ifo[b * NQKV + 1024 + d];
        float kv = g_qkv[b * NQKV + 1024 + d];
        float qv = g_qkv[b * NQKV + d];
        float nn = fv * n_in[b * Hdim + d] + iv * kv;
        out_n[b * Hdim + d] = nn;
        psum += qv * nn;
    }
    red[tid] = psum;
    __syncthreads();
#pragma unroll
    for (int s = 128; s > 0; s >>= 1) {
        if (tid < s) red[tid] += red[tid + s];
        __syncthreads();
    }
    if (tid == 0) g_denom[b] = fmaxf(red[0], 1e-6f);
}

// ---------------------------------------------------------------------------
// K3: C update + fused h_lin, cp.async-staged chunks — 3-buffer ring.
// 148 persistent CTAs x 1024 threads. Tile = (b, ht): 128 rows x 1024 cols,
// 8 chunks of 16 rows (64KB). Ring of 3 smem buffers (192KB): while chunk c
// is computed, chunks c+1 AND c+2 are in flight (128KB outstanding reads).
// One barrier per chunk.
// ---------------------------------------------------------------------------
#define HH (Hdim * Hdim)
#define CHUNK_FLOATS (16 * 1024)       // 16 rows x 1024 cols
#define CHUNK_BYTES  (CHUNK_FLOATS * 4)

__global__ __launch_bounds__(1024, 1) void update_C_kernel(
    const float* __restrict__ C, float* __restrict__ outC)
{
    extern __shared__ float dynbuf[];          // [3][16][1024]
    __shared__ float qs[128], fs[128], iks[128];
    __shared__ float4 sbuf[4][256];

    const int tid = threadIdx.x;
    const int rg = tid >> 8;        // 0..3
    const int cq = tid & 255;       // 0..255
    const int ct = cq * 4;
    const uint32_t sbase = smem_u32(dynbuf);

    for (int tile = blockIdx.x; tile < Bsz * 8; tile += 148) {
        const int b  = tile >> 3;
        const int ht = tile & 7;

        __syncthreads();   // previous tile fully consumed (smem reuse)
        if (tid < 128) {
            int h = ht * 128 + tid;
            qs[tid]  = g_qkv[b * NQKV + h];
            float kv = g_qkv[b * NQKV + 1024 + h];
            float iv = g_ifo[b * NQKV + h];
            fs[tid]  = g_ifo[b * NQKV + 1024 + h];
            iks[tid] = iv * kv;
        }

        const float* __restrict__ srcT = C    + (size_t)b * HH + (size_t)ht * 128 * Hdim;
        float* __restrict__       dstT = outC + (size_t)b * HH + (size_t)ht * 128 * Hdim;

        // prologue: issue chunks 0 and 1 into ring slots 0, 1
#pragma unroll
        for (int pc = 0; pc < 2; pc++) {
            const float* s2 = srcT + (size_t)pc * 16 * Hdim;
            uint32_t d2 = sbase + (uint32_t)(pc * CHUNK_BYTES);
#pragma unroll
            for (int r = 0; r < 4; r++) {
                int jj = r * 4 + rg;
                cp_async16(d2 + (uint32_t)(jj * 1024 + ct) * 4,
                           s2 + (size_t)jj * Hdim + ct);
            }
            asm volatile("cp.async.commit_group;");
        }
        __syncthreads();   // qs/fs/iks visible

        const float4 v4 = *(const float4*)(g_qkv + b * NQKV + 2048 + ct);
        float4 acc = make_float4(0.f, 0.f, 0.f, 0.f);

        for (int c = 0; c < 8; c++) {
            // chunk c has landed when <=1 group (chunk c+1) remains outstanding
            if (c < 7) {
                asm volatile("cp.async.wait_group 1;");
            } else {
                asm volatile("cp.async.wait_group 0;");
            }
            __syncthreads();   // buffer c complete for all threads

            const int slot = c % 3;
            const float* buf = dynbuf + slot * CHUNK_FLOATS;
            float* __restrict__ dstC = dstT + (size_t)c * 16 * Hdim;
#pragma unroll
            for (int s = 0; s < 4; s++) {
                int jj = s * 4 + rg;
                int j  = c * 16 + jj;
                float4 c4 = *(const float4*)(buf + jj * 1024 + ct);
                const float fv = fs[j], ik = iks[j], qv = qs[j];
                float4 cn;
                cn.x = fmaf(fv, c4.x, ik * v4.x);
                cn.y = fmaf(fv, c4.y, ik * v4.y);
                cn.z = fmaf(fv, c4.z, ik * v4.z);
                cn.w = fmaf(fv, c4.w, ik * v4.w);
                __stcs((float4*)(dstC + (size_t)jj * Hdim + ct), cn);
                acc.x = fmaf(qv, cn.x, acc.x);
                acc.y = fmaf(qv, cn.y, acc.y);
                acc.z = fmaf(qv, cn.z, acc.z);
                acc.w = fmaf(qv, cn.w, acc.w);
            }

            // issue chunk c+2 into slot (c+2)%3 (its last reader was chunk
            // c-1, finished before this iteration's barrier)
            if (c + 2 < 8) {
                const float* s2 = srcT + (size_t)(c + 2) * 16 * Hdim;
                uint32_t d2 = sbase + (uint32_t)(((c + 2) % 3) * CHUNK_BYTES);
#pragma unroll
                for (int r = 0; r < 4; r++) {
                    int jj = r * 4 + rg;
                    cp_async16(d2 + (uint32_t)(jj * 1024 + ct) * 4,
                               s2 + (size_t)jj * Hdim + ct);
                }
                asm volatile("cp.async.commit_group;");
            }
        }

        sbuf[rg][cq] = acc;
        __syncthreads();
        if (tid < 256) {
            float4 s0 = sbuf[0][tid], s1 = sbuf[1][tid];
            float4 s2 = sbuf[2][tid], s3 = sbuf[3][tid];
            float4 r;
            r.x = (s0.x + s1.x) + (s2.x + s3.x);
            r.y = (s0.y + s1.y) + (s2.y + s3.y);
            r.z = (s0.z + s1.z) + (s2.z + s3.z);
            r.w = (s0.w + s1.w) + (s2.w + s3.w);
            *(float4*)(g_hpart + ht * (Bsz * Hdim) + (b << 10) + tid * 4) = r;
        }
    }
}

// ---------------------------------------------------------------------------
// K4: h_new = o * (sum_ht h_lin_part) / denom
// ---------------------------------------------------------------------------
__global__ __launch_bounds__(256) void finalize_h_kernel(float* __restrict__ out_h)
{
    const int idx = blockIdx.x * 256 + threadIdx.x;
    const int b = idx >> 10;
    const int d = idx & 1023;
    float hl = 0.f;
#pragma unroll
    for (int p = 0; p < 8; p++) hl += g_hpart[p * (Bsz * Hdim) + (b << 10) + d];
    out_h[idx] = g_ifo[b * NQKV + 2048 + d] * hl / g_denom[b];
}

// ---------------------------------------------------------------------------
extern "C" void kernel_launch(void* const* d_in, const int* in_sizes, int n_in,
                              void* d_out, int out_size)
{
    const float *x = 0, *C = 0, *n_in_p = 0;
    const float *W_proj = 0, *b_proj = 0, *W_gates = 0, *b_gates = 0;

    const float* trio[3] = {0, 0, 0};
    int ntrio = 0;
    for (int idx = 0; idx < n_in; idx++) {
        const float* p = (const float*)d_in[idx];
        switch (in_sizes[idx]) {
            case 134217728: C       = p; break;
            case 4194304:   W_proj  = p; break;
            case 3145728:   W_gates = p; break;
            case 4096:      b_proj  = p; break;
            case 3072:      b_gates = p; break;
            case 131072:    if (ntrio < 3) trio[ntrio++] = p; break;
            default: break;
        }
    }
    n_in_p = trio[1];
    if (in_sizes[0] == 131072) x = trio[0];
    else                       x = trio[2];

    float* out   = (float*)d_out;
    float* out_h = out;
    float* out_C = out + Bsz * Hdim;
    float* out_n = out + Bsz * Hdim + (size_t)Bsz * Hdim * Hdim;

    cudaFuncSetAttribute(update_C_kernel,
                         cudaFuncAttributeMaxDynamicSharedMemorySize,
                         3 * CHUNK_BYTES);

    dim3 ggrid(NQKV / 128, 1, KSPLIT);   // (24, 1, 6)
    gemm_main_kernel<0><<<ggrid, 256>>>(x, W_proj);
    gemm_epi_kernel<0><<<OUTMN / 256, 256>>>(b_proj);
    gemm_main_kernel<1><<<ggrid, 256>>>(nullptr, W_gates);
    gemm_epi_kernel<1><<<OUTMN / 256, 256>>>(b_gates);
    nnew_denom_kernel<<<Bsz, 256>>>(n_in_p, out_n);
    update_C_kernel<<<148, 1024, 3 * CHUNK_BYTES>>>(C, out_C);
    finalize_h_kernel<<<(Bsz * Hdim) / 256, 256>>>(out_h);
}

// round 17
// speedup vs baseline: 1.0026x; 1.0026x over previous
#include <cuda_runtime.h>
#include <math.h>
#include <stdint.h>

// ---------------------------------------------------------------------------
// mLSTM cell, B=128, D_IN=1024, H=1024  (SIMT + FFMA2; plain sm_103 target)
// output: concat[ h_new (128*1024), C_new (128*1024*1024), n_new (128*1024) ]
// ---------------------------------------------------------------------------

#define Bsz   128
#define Hdim  1024
#define NQKV  3072
#define KSPLIT 6
#define OUTMN (Bsz * NQKV)

__device__ float g_qkv[Bsz * NQKV];        // [b][ q | k | v ]
__device__ float g_ifo[Bsz * NQKV];        // [b][ i | f | o ]
__device__ float g_part[KSPLIT * OUTMN];
__device__ float g_hpart[8 * Bsz * Hdim];
__device__ float g_denom[Bsz];

// ---- packed f32x2 helpers ----
__device__ __forceinline__ unsigned long long pack_dup(float a) {
    unsigned long long r;
    uint32_t au = __float_as_uint(a);
    asm("mov.b64 %0, {%1, %1};" : "=l"(r) : "r"(au));
    return r;
}
__device__ __forceinline__ void fma2(unsigned long long& d,
                                     unsigned long long a,
                                     unsigned long long b) {
    asm("fma.rn.f32x2 %0, %1, %2, %0;" : "+l"(d) : "l"(a), "l"(b));
}
__device__ __forceinline__ float2 unpack2(unsigned long long v) {
    uint32_t lo, hi;
    asm("mov.b64 {%0, %1}, %2;" : "=r"(lo), "=r"(hi) : "l"(v));
    return make_float2(__uint_as_float(lo), __uint_as_float(hi));
}
__device__ __forceinline__ uint32_t smem_u32(const void* p) {
    uint32_t a;
    asm("{ .reg .u64 t; cvta.to.shared.u64 t, %1; cvt.u32.u64 %0, t; }"
        : "=r"(a) : "l"(p));
    return a;
}
__device__ __forceinline__ void cp_async16(uint32_t dst, const float* src) {
    asm volatile("cp.async.cg.shared.global [%0], [%1], 16;"
                 :: "r"(dst), "l"(src));
}

// ---------------------------------------------------------------------------
// Split-K GEMM mainloop (round-9/12 form): BM=128 BN=128 BK=16,
// 256 threads, 8x8 FFMA2 tile, double-buffered smem. grid (24,1,6).
// ---------------------------------------------------------------------------
template <int MODE>
__global__ __launch_bounds__(256) void gemm_main_kernel(
    const float* __restrict__ Aext, const float* __restrict__ W)
{
    const float* __restrict__ A = (MODE == 0) ? Aext : (const float*)(g_qkv + 2048);
    const int lda = (MODE == 0) ? 1024 : NQKV;
    const int ldw = (MODE == 0) ? 4096 : 3072;

    __shared__ float As[2][16][132];
    __shared__ float Bs[2][16][128];

    const int tid = threadIdx.x;
    const int bn = blockIdx.x * 128;
    const int kz = blockIdx.z;

    const int aRow = tid >> 1;
    const int aK   = (tid & 1) * 8;
    const int bRow = tid >> 4;
    const int bCol = (tid & 15) * 8;

    const int mrow = (tid >> 4) * 8;
    const int ncol = (tid & 15) * 8;

    unsigned long long acc2[8][4];
#pragma unroll
    for (int r = 0; r < 8; r++)
#pragma unroll
        for (int c = 0; c < 4; c++) acc2[r][c] = 0ull;

    const int it0   = kz * 10 + (kz < 4 ? kz : 4);
    const int iters = (kz < 4) ? 11 : 10;

    {
        const int k0 = it0 * 16;
        float4 av0 = *(const float4*)(A + (size_t)aRow * lda + k0 + aK);
        float4 av1 = *(const float4*)(A + (size_t)aRow * lda + k0 + aK + 4);
        As[0][aK + 0][aRow] = av0.x; As[0][aK + 1][aRow] = av0.y;
        As[0][aK + 2][aRow] = av0.z; As[0][aK + 3][aRow] = av0.w;
        As[0][aK + 4][aRow] = av1.x; As[0][aK + 5][aRow] = av1.y;
        As[0][aK + 6][aRow] = av1.z; As[0][aK + 7][aRow] = av1.w;
        float4 bv0 = *(const float4*)(W + (size_t)(k0 + bRow) * ldw + bn + bCol);
        float4 bv1 = *(const float4*)(W + (size_t)(k0 + bRow) * ldw + bn + bCol + 4);
        *(float4*)&Bs[0][bRow][bCol]     = bv0;
        *(float4*)&Bs[0][bRow][bCol + 4] = bv1;
    }
    __syncthreads();

    int cur = 0;
    for (int it = 0; it < iters; it++) {
        const bool has = (it + 1 < iters);
        float4 av0, av1, bv0, bv1;
        if (has) {
            const int k0 = (it0 + it + 1) * 16;
            av0 = *(const float4*)(A + (size_t)aRow * lda + k0 + aK);
            av1 = *(const float4*)(A + (size_t)aRow * lda + k0 + aK + 4);
            bv0 = *(const float4*)(W + (size_t)(k0 + bRow) * ldw + bn + bCol);
            bv1 = *(const float4*)(W + (size_t)(k0 + bRow) * ldw + bn + bCol + 4);
        }

#pragma unroll
        for (int kk = 0; kk < 16; kk++) {
            float4 a0 = *(const float4*)&As[cur][kk][mrow];
            float4 a1 = *(const float4*)&As[cur][kk][mrow + 4];
            ulonglong2 bb0 = *(const ulonglong2*)&Bs[cur][kk][ncol];
            ulonglong2 bb1 = *(const ulonglong2*)&Bs[cur][kk][ncol + 4];
            unsigned long long a2[8];
            a2[0] = pack_dup(a0.x); a2[1] = pack_dup(a0.y);
            a2[2] = pack_dup(a0.z); a2[3] = pack_dup(a0.w);
            a2[4] = pack_dup(a1.x); a2[5] = pack_dup(a1.y);
            a2[6] = pack_dup(a1.z); a2[7] = pack_dup(a1.w);
#pragma unroll
            for (int r = 0; r < 8; r++) {
                fma2(acc2[r][0], a2[r], bb0.x);
                fma2(acc2[r][1], a2[r], bb0.y);
                fma2(acc2[r][2], a2[r], bb1.x);
                fma2(acc2[r][3], a2[r], bb1.y);
            }
        }

        if (has) {
            const int nxt = cur ^ 1;
            As[nxt][aK + 0][aRow] = av0.x; As[nxt][aK + 1][aRow] = av0.y;
            As[nxt][aK + 2][aRow] = av0.z; As[nxt][aK + 3][aRow] = av0.w;
            As[nxt][aK + 4][aRow] = av1.x; As[nxt][aK + 5][aRow] = av1.y;
            As[nxt][aK + 6][aRow] = av1.z; As[nxt][aK + 7][aRow] = av1.w;
            *(float4*)&Bs[nxt][bRow][bCol]     = bv0;
            *(float4*)&Bs[nxt][bRow][bCol + 4] = bv1;
            __syncthreads();
            cur = nxt;
        }
    }

    float* __restrict__ part = g_part + (size_t)kz * OUTMN;
#pragma unroll
    for (int r = 0; r < 8; r++) {
        int m = mrow + r;
        float2 p0 = unpack2(acc2[r][0]);
        float2 p1 = unpack2(acc2[r][1]);
        float2 p2 = unpack2(acc2[r][2]);
        float2 p3 = unpack2(acc2[r][3]);
        *(float4*)(part + (size_t)m * NQKV + bn + ncol) =
            make_float4(p0.x, p0.y, p1.x, p1.y);
        *(float4*)(part + (size_t)m * NQKV + bn + ncol + 4) =
            make_float4(p2.x, p2.y, p3.x, p3.y);
    }
}

// ---------------------------------------------------------------------------
// GEMM epilogue
// ---------------------------------------------------------------------------
template <int MODE>
__global__ __launch_bounds__(256) void gemm_epi_kernel(const float* __restrict__ bias)
{
    const int idx = blockIdx.x * 256 + threadIdx.x;
    const int nn = idx % NQKV;
    float v = bias[nn];
#pragma unroll
    for (int p = 0; p < KSPLIT; p++) v += g_part[(size_t)p * OUTMN + idx];
    if (MODE == 0) {
        if (nn < 2048) v = tanhf(v);
        g_qkv[idx] = v;
    } else {
        g_ifo[idx] = 1.0f / (1.0f + expf(-v));
    }
}

// ---------------------------------------------------------------------------
// n_new + denom
// ---------------------------------------------------------------------------
__global__ __launch_bounds__(256) void nnew_denom_kernel(
    const float* __restrict__ n_in, float* __restrict__ out_n)
{
    const int b = blockIdx.x;
    const int tid = threadIdx.x;
    __shared__ float red[256];

    float psum = 0.f;
#pragma unroll
    for (int d = tid; d < Hdim; d += 256) {
        float iv = g_ifo[b * NQKV + d];
        float fv = g_ifo[b * NQKV + 1024 + d];
        float kv = g_qkv[b * NQKV + 1024 + d];
        float qv = g_qkv[b * NQKV + d];
        float nn = fv * n_in[b * Hdim + d] + iv * kv;
        out_n[b * Hdim + d] = nn;
        psum += qv * nn;
    }
    red[tid] = psum;
    __syncthreads();
#pragma unroll
    for (int s = 128; s > 0; s >>= 1) {
        if (tid < s) red[tid] += red[tid + s];
        __syncthreads();
    }
    if (tid == 0) g_denom[b] = fmaxf(red[0], 1e-6f);
}

// ---------------------------------------------------------------------------
// K3: C update + fused h_lin, cp.async 3-slot ring, BARRIER-FREE chunk loop.
// Key property: each thread reads back exactly the smem it cp.async'd itself
// (same jj/ct set), so cp.async.wait_group alone gives visibility — no
// __syncthreads needed per chunk. Chunk c+2 is issued BEFORE computing chunk
// c, so 2 chunks (128KB) are in flight during every compute phase and warps
// free-run without lockstep.
// 148 persistent CTAs x 1024 threads; tile = (b, ht) = 128 rows x 1024 cols,
// 8 chunks of 16 rows.
// ---------------------------------------------------------------------------
#define HH (Hdim * Hdim)
#define CHUNK_FLOATS (16 * 1024)
#define CHUNK_BYTES  (CHUNK_FLOATS * 4)

__global__ __launch_bounds__(1024, 1) void update_C_kernel(
    const float* __restrict__ C, float* __restrict__ outC)
{
    extern __shared__ float dynbuf[];          // [3][16][1024]
    __shared__ float qs[128], fs[128], iks[128];
    __shared__ float4 sbuf[4][256];

    const int tid = threadIdx.x;
    const int rg = tid >> 8;        // 0..3
    const int cq = tid & 255;       // 0..255
    const int ct = cq * 4;
    const uint32_t sbase = smem_u32(dynbuf);

    for (int tile = blockIdx.x; tile < Bsz * 8; tile += 148) {
        const int b  = tile >> 3;
        const int ht = tile & 7;

        __syncthreads();   // previous tile fully consumed (smem + sbuf reuse)
        if (tid < 128) {
            int h = ht * 128 + tid;
            qs[tid]  = g_qkv[b * NQKV + h];
            float kv = g_qkv[b * NQKV + 1024 + h];
            float iv = g_ifo[b * NQKV + h];
            fs[tid]  = g_ifo[b * NQKV + 1024 + h];
            iks[tid] = iv * kv;
        }

        const float* __restrict__ srcT = C    + (size_t)b * HH + (size_t)ht * 128 * Hdim;
        float* __restrict__       dstT = outC + (size_t)b * HH + (size_t)ht * 128 * Hdim;

        // prologue: issue chunks 0 and 1 into ring slots 0, 1
#pragma unroll
        for (int pc = 0; pc < 2; pc++) {
            const float* s2 = srcT + (size_t)pc * 16 * Hdim;
            uint32_t d2 = sbase + (uint32_t)(pc * CHUNK_BYTES);
#pragma unroll
            for (int r = 0; r < 4; r++) {
                int jj = r * 4 + rg;
                cp_async16(d2 + (uint32_t)(jj * 1024 + ct) * 4,
                           s2 + (size_t)jj * Hdim + ct);
            }
            asm volatile("cp.async.commit_group;");
        }
        __syncthreads();   // qs/fs/iks visible to all threads

        const float4 v4 = *(const float4*)(g_qkv + b * NQKV + 2048 + ct);
        float4 acc = make_float4(0.f, 0.f, 0.f, 0.f);

        for (int c = 0; c < 8; c++) {
            // per-thread wait: own chunk-c copies complete (c+1 may pend)
            if (c < 7) {
                asm volatile("cp.async.wait_group 1;");
            } else {
                asm volatile("cp.async.wait_group 0;");
            }

            // issue chunk c+2 BEFORE compute: slot (c+2)%3's last reader was
            // chunk c-1 — this same thread — already consumed. 2 chunks in
            // flight during the compute below.
            if (c + 2 < 8) {
                const float* s2 = srcT + (size_t)(c + 2) * 16 * Hdim;
                uint32_t d2 = sbase + (uint32_t)(((c + 2) % 3) * CHUNK_BYTES);
#pragma unroll
                for (int r = 0; r < 4; r++) {
                    int jj = r * 4 + rg;
                    cp_async16(d2 + (uint32_t)(jj * 1024 + ct) * 4,
                               s2 + (size_t)jj * Hdim + ct);
                }
            }
            asm volatile("cp.async.commit_group;");   // empty group when c+2>=8

            const int slot = c % 3;
            const float* buf = dynbuf + slot * CHUNK_FLOATS;
            float* __restrict__ dstC = dstT + (size_t)c * 16 * Hdim;
#pragma unroll
            for (int s = 0; s < 4; s++) {
                int jj = s * 4 + rg;
                int j  = c * 16 + jj;
                float4 c4 = *(const float4*)(buf + jj * 1024 + ct);
                const float fv = fs[j], ik = iks[j], qv = qs[j];
                float4 cn;
                cn.x = fmaf(fv, c4.x, ik * v4.x);
                cn.y = fmaf(fv, c4.y, ik * v4.y);
                cn.z = fmaf(fv, c4.z, ik * v4.z);
                cn.w = fmaf(fv, c4.w, ik * v4.w);
                __stcs((float4*)(dstC + (size_t)jj * Hdim + ct), cn);
                acc.x = fmaf(qv, cn.x, acc.x);
                acc.y = fmaf(qv, cn.y, acc.y);
                acc.z = fmaf(qv, cn.z, acc.z);
                acc.w = fmaf(qv, cn.w, acc.w);
            }
        }

        sbuf[rg][cq] = acc;
        __syncthreads();
        if (tid < 256) {
            float4 s0 = sbuf[0][tid], s1 = sbuf[1][tid];
            float4 s2 = sbuf[2][tid], s3 = sbuf[3][tid];
            float4 r;
            r.x = (s0.x + s1.x) + (s2.x + s3.x);
            r.y = (s0.y + s1.y) + (s2.y + s3.y);
            r.z = (s0.z + s1.z) + (s2.z + s3.z);
            r.w = (s0.w + s1.w) + (s2.w + s3.w);
            *(float4*)(g_hpart + ht * (Bsz * Hdim) + (b << 10) + tid * 4) = r;
        }
    }
}

// ---------------------------------------------------------------------------
// K4: h_new = o * (sum_ht h_lin_part) / denom
// ---------------------------------------------------------------------------
__global__ __launch_bounds__(256) void finalize_h_kernel(float* __restrict__ out_h)
{
    const int idx = blockIdx.x * 256 + threadIdx.x;
    const int b = idx >> 10;
    const int d = idx & 1023;
    float hl = 0.f;
#pragma unroll
    for (int p = 0; p < 8; p++) hl += g_hpart[p * (Bsz * Hdim) + (b << 10) + d];
    out_h[idx] = g_ifo[b * NQKV + 2048 + d] * hl / g_denom[b];
}

// ---------------------------------------------------------------------------
extern "C" void kernel_launch(void* const* d_in, const int* in_sizes, int n_in,
                              void* d_out, int out_size)
{
    const float *x = 0, *C = 0, *n_in_p = 0;
    const float *W_proj = 0, *b_proj = 0, *W_gates = 0, *b_gates = 0;

    const float* trio[3] = {0, 0, 0};
    int ntrio = 0;
    for (int idx = 0; idx < n_in; idx++) {
        const float* p = (const float*)d_in[idx];
        switch (in_sizes[idx]) {
            case 134217728: C       = p; break;
            case 4194304:   W_proj  = p; break;
            case 3145728:   W_gates = p; break;
            case 4096:      b_proj  = p; break;
            case 3072:      b_gates = p; break;
            case 131072:    if (ntrio < 3) trio[ntrio++] = p; break;
            default: break;
        }
    }
    n_in_p = trio[1];
    if (in_sizes[0] == 131072) x = trio[0];
    else                       x = trio[2];

    float* out   = (float*)d_out;
    float* out_h = out;
    float* out_C = out + Bsz * Hdim;
    float* out_n = out + Bsz * Hdim + (size_t)Bsz * Hdim * Hdim;

    cudaFuncSetAttribute(update_C_kernel,
                         cudaFuncAttributeMaxDynamicSharedMemorySize,
                         3 * CHUNK_BYTES);

    dim3 ggrid(NQKV / 128, 1, KSPLIT);   // (24, 1, 6)
    gemm_main_kernel<0><<<ggrid, 256>>>(x, W_proj);
    gemm_epi_kernel<0><<<OUTMN / 256, 256>>>(b_proj);
    gemm_main_kernel<1><<<ggrid, 256>>>(nullptr, W_gates);
    gemm_epi_kernel<1><<<OUTMN / 256, 256>>>(b_gates);
    nnew_denom_kernel<<<Bsz, 256>>>(n_in_p, out_n);
    update_C_kernel<<<148, 1024, 3 * CHUNK_BYTES>>>(C, out_C);
    finalize_h_kernel<<<(Bsz * Hdim) / 256, 256>>>(out_h);
}